// round 15
// baseline (speedup 1.0000x reference)
#include <cuda_runtime.h>
#include <cstdint>

// ---------------------------------------------------------------------------
// GaussSpatialConv: out[i,:] = softmax_j( -||x_i - y_j||^2 / (2*sigma^2) ) @ fea
// B=1, N=M=12288, D=16, sigma=0.1.
//
//   k_prep : pack y into float4 rows, negated
//   k_min  : partial min_j d2 per query over M/SPL chunk   -> pmin[SPL][N]
//   k_acc  : s = sum exp2(C*(d2-mind)), acc = sum p*fea    -> ps/pacc partials
//   k_norm : reduce partials over SPL, out = acc/s
//
// R10 change: SPL 12 -> 24. Per-CTA j-chunk working set = 512*(64+16)B = 40KB,
// so ~5 resident CTAs/SM (200KB) fit L1 (228KB). R9's 80KB/CTA thrashed L1 and
// pushed every hot-loop load to L2 (~240 cyc) -> measured 405us vs ~102us FMA
// floor. L1-resident, FMA (11.5 SM-cyc/iter) and LSU (9.1) become the binders.
// ---------------------------------------------------------------------------

typedef unsigned long long ull;

#define TPB 128      // threads per CTA in the heavy kernels
#define QPT 2        // queries per thread (packed into f32x2 lanes)
#define SPL 24       // splits of the M (j) dimension (CH = 12288/24 = 512)
#define DD  16       // feature dim (fixed for this problem)

// 32 MB static scratch (no allocations allowed). Layout computed at launch.
__device__ __align__(256) float g_scratch[8u << 20];

// ---- f32x2 helpers (Blackwell packed fp32) --------------------------------
__device__ __forceinline__ ull pk2(float lo, float hi) {
    ull r; asm("mov.b64 %0, {%1, %2};" : "=l"(r) : "f"(lo), "f"(hi)); return r;
}
__device__ __forceinline__ void upk2(ull v, float& lo, float& hi) {
    asm("mov.b64 {%0, %1}, %2;" : "=f"(lo), "=f"(hi) : "l"(v));
}
__device__ __forceinline__ ull add2(ull a, ull b) {
    ull r; asm("add.rn.f32x2 %0, %1, %2;" : "=l"(r) : "l"(a), "l"(b)); return r;
}
__device__ __forceinline__ ull mul2(ull a, ull b) {
    ull r; asm("mul.rn.f32x2 %0, %1, %2;" : "=l"(r) : "l"(a), "l"(b)); return r;
}
__device__ __forceinline__ ull fma2(ull a, ull b, ull c) {
    ull r; asm("fma.rn.f32x2 %0, %1, %2, %3;" : "=l"(r) : "l"(a), "l"(b), "l"(c)); return r;
}
// MUFU.EX2 — hardware exp2 approximation (~2 ulp; args are <= 0 here)
__device__ __forceinline__ float ex2(float a) {
    float r; asm("ex2.approx.ftz.f32 %0, %1;" : "=f"(r) : "f"(a)); return r;
}

// ---- k_prep: y4[j] = (-y0, -y1, -y2, 0) ------------------------------------
__global__ void k_prep(const float* __restrict__ y, long long off_y4, int M) {
    float4* y4 = reinterpret_cast<float4*>(g_scratch + off_y4);
    int j = blockIdx.x * blockDim.x + threadIdx.x;
    if (j < M) {
        float a = y[3 * j], b = y[3 * j + 1], c = y[3 * j + 2];
        y4[j] = make_float4(-a, -b, -c, 0.0f);
    }
}

// ---- k_min: partial min of d2 over this CTA's j-chunk ----------------------
__global__ void __launch_bounds__(TPB) k_min(
    const float* __restrict__ x,
    long long off_y4, long long off_pmin,
    int N, int M, int CH)
{
    const float4* __restrict__ y4 = reinterpret_cast<const float4*>(g_scratch + off_y4);
    float* __restrict__ pmin = g_scratch + off_pmin;

    int s  = blockIdx.x % SPL;
    int qb = blockIdx.x / SPL;
    int i0 = (qb * TPB + threadIdx.x) * QPT;
    int i1 = i0 + 1;
    int a0 = min(i0, N - 1), a1 = min(i1, N - 1);

    ull xx = pk2(x[3 * a0],     x[3 * a1]);
    ull xy = pk2(x[3 * a0 + 1], x[3 * a1 + 1]);
    ull xz = pk2(x[3 * a0 + 2], x[3 * a1 + 2]);

    int j0 = s * CH;
    int j1 = min(M, j0 + CH);
    float m0 = 3.4e38f, m1 = 3.4e38f;

    #pragma unroll 4
    for (int j = j0; j < j1; ++j) {
        float4 yv = y4[j];
        ull dx = add2(xx, pk2(yv.x, yv.x));
        ull dy = add2(xy, pk2(yv.y, yv.y));
        ull dz = add2(xz, pk2(yv.z, yv.z));
        ull d2 = mul2(dx, dx);
        d2 = fma2(dy, dy, d2);
        d2 = fma2(dz, dz, d2);
        float d20, d21; upk2(d2, d20, d21);
        m0 = fminf(m0, d20);
        m1 = fminf(m1, d21);
    }
    if (i0 < N) pmin[(size_t)s * N + i0] = m0;
    if (i1 < N) pmin[(size_t)s * N + i1] = m1;
}

// ---- k_acc: partial softmax numerator/denominator --------------------------
__global__ void __launch_bounds__(TPB) k_acc(
    const float* __restrict__ x,
    const ulonglong2* __restrict__ fea,   // M rows x 4 x ulonglong2 (= 16 floats)
    long long off_y4, long long off_pmin, long long off_ps, long long off_pacc,
    int N, int M, int CH)
{
    const float Cc = -72.13475204444817f;  // -log2(e) / (2 * 0.1^2)

    const float4* __restrict__ y4 = reinterpret_cast<const float4*>(g_scratch + off_y4);
    const float* __restrict__ pmin = g_scratch + off_pmin;
    float* __restrict__ ps   = g_scratch + off_ps;
    float* __restrict__ pacc = g_scratch + off_pacc;

    int s  = blockIdx.x % SPL;
    int qb = blockIdx.x / SPL;
    int i0 = (qb * TPB + threadIdx.x) * QPT;
    int i1 = i0 + 1;
    int a0 = min(i0, N - 1), a1 = min(i1, N - 1);

    ull xx = pk2(x[3 * a0],     x[3 * a1]);
    ull xy = pk2(x[3 * a0 + 1], x[3 * a1 + 1]);
    ull xz = pk2(x[3 * a0 + 2], x[3 * a1 + 2]);

    // global min d2 per query (reduce the SPL partials)
    float md0 = 3.4e38f, md1 = 3.4e38f;
    #pragma unroll
    for (int sp = 0; sp < SPL; ++sp) {
        md0 = fminf(md0, pmin[(size_t)sp * N + a0]);
        md1 = fminf(md1, pmin[(size_t)sp * N + a1]);
    }
    ull C2 = pk2(Cc, Cc);
    ull K2 = pk2(-Cc * md0, -Cc * md1);   // arg = C*d2 + K = C*(d2 - mind) <= 0

    ull acc0[8], acc1[8];
    #pragma unroll
    for (int k = 0; k < 8; ++k) { acc0[k] = 0ull; acc1[k] = 0ull; }
    float s0 = 0.0f, s1 = 0.0f;

    int j0 = s * CH;
    int j1 = min(M, j0 + CH);

    #pragma unroll 2
    for (int j = j0; j < j1; ++j) {
        float4 yv = y4[j];
        // identical d2 sequence to k_min -> arg <= 0 bitwise-guaranteed
        ull dx = add2(xx, pk2(yv.x, yv.x));
        ull dy = add2(xy, pk2(yv.y, yv.y));
        ull dz = add2(xz, pk2(yv.z, yv.z));
        ull d2 = mul2(dx, dx);
        d2 = fma2(dy, dy, d2);
        d2 = fma2(dz, dz, d2);
        ull arg = fma2(d2, C2, K2);
        float g0, g1; upk2(arg, g0, g1);
        float p0 = ex2(g0);
        float p1 = ex2(g1);
        s0 += p0;
        s1 += p1;
        ull pp0 = pk2(p0, p0);
        ull pp1 = pk2(p1, p1);

        const ulonglong2* fr = fea + (size_t)j * 4;
        ulonglong2 f0 = fr[0];
        ulonglong2 f1 = fr[1];
        ulonglong2 f2 = fr[2];
        ulonglong2 f3 = fr[3];
        acc0[0] = fma2(pp0, f0.x, acc0[0]);  acc1[0] = fma2(pp1, f0.x, acc1[0]);
        acc0[1] = fma2(pp0, f0.y, acc0[1]);  acc1[1] = fma2(pp1, f0.y, acc1[1]);
        acc0[2] = fma2(pp0, f1.x, acc0[2]);  acc1[2] = fma2(pp1, f1.x, acc1[2]);
        acc0[3] = fma2(pp0, f1.y, acc0[3]);  acc1[3] = fma2(pp1, f1.y, acc1[3]);
        acc0[4] = fma2(pp0, f2.x, acc0[4]);  acc1[4] = fma2(pp1, f2.x, acc1[4]);
        acc0[5] = fma2(pp0, f2.y, acc0[5]);  acc1[5] = fma2(pp1, f2.y, acc1[5]);
        acc0[6] = fma2(pp0, f3.x, acc0[6]);  acc1[6] = fma2(pp1, f3.x, acc1[6]);
        acc0[7] = fma2(pp0, f3.y, acc0[7]);  acc1[7] = fma2(pp1, f3.y, acc1[7]);
    }

    if (i0 < N) {
        ps[(size_t)s * N + i0] = s0;
        float4* dst = reinterpret_cast<float4*>(pacc + ((size_t)s * N + i0) * DD);
        #pragma unroll
        for (int k = 0; k < 4; ++k) {
            float lo0, hi0, lo1, hi1;
            upk2(acc0[2 * k],     lo0, hi0);
            upk2(acc0[2 * k + 1], lo1, hi1);
            dst[k] = make_float4(lo0, hi0, lo1, hi1);
        }
    }
    if (i1 < N) {
        ps[(size_t)s * N + i1] = s1;
        float4* dst = reinterpret_cast<float4*>(pacc + ((size_t)s * N + i1) * DD);
        #pragma unroll
        for (int k = 0; k < 4; ++k) {
            float lo0, hi0, lo1, hi1;
            upk2(acc1[2 * k],     lo0, hi0);
            upk2(acc1[2 * k + 1], lo1, hi1);
            dst[k] = make_float4(lo0, hi0, lo1, hi1);
        }
    }
}

// ---- k_norm: reduce over splits and normalize ------------------------------
__global__ void k_norm(long long off_ps, long long off_pacc,
                       float* __restrict__ out, int N)
{
    const float* __restrict__ ps   = g_scratch + off_ps;
    const float* __restrict__ pacc = g_scratch + off_pacc;
    int idx = blockIdx.x * blockDim.x + threadIdx.x;
    if (idx >= N * DD) return;
    int i = idx / DD;
    int d = idx % DD;
    float st = 0.0f, at = 0.0f;
    #pragma unroll
    for (int sp = 0; sp < SPL; ++sp) {
        st += ps[(size_t)sp * N + i];
        at += pacc[((size_t)sp * N + i) * DD + d];
    }
    out[idx] = at / st;
}

// ---------------------------------------------------------------------------
extern "C" void kernel_launch(void* const* d_in, const int* in_sizes, int n_in,
                              void* d_out, int out_size) {
    const float* x   = (const float*)d_in[0];   // [N,3]
    const float* y   = (const float*)d_in[1];   // [M,3]
    const float* fea = (const float*)d_in[2];   // [M,16]
    float* out = (float*)d_out;                 // [N,16]

    int N = in_sizes[0] / 3;
    int M = in_sizes[1] / 3;

    auto r4 = [](long long v) { return (v + 3) & ~3LL; };
    long long off_y4   = 0;
    long long off_pmin = r4(off_y4 + 4LL * M);
    long long off_ps   = r4(off_pmin + (long long)SPL * N);
    long long off_pacc = r4(off_ps + (long long)SPL * N);
    // total: 4M + 2*SPL*N + SPL*N*16  ~= 5.4M floats < 8M capacity

    int CH = (M + SPL - 1) / SPL;                 // j-chunk per split (512)
    int QB = (N + TPB * QPT - 1) / (TPB * QPT);   // query blocks (48)

    k_prep<<<(M + 255) / 256, 256>>>(y, off_y4, M);
    k_min<<<QB * SPL, TPB>>>(x, off_y4, off_pmin, N, M, CH);
    k_acc<<<QB * SPL, TPB>>>(x, (const ulonglong2*)fea,
                             off_y4, off_pmin, off_ps, off_pacc, N, M, CH);
    k_norm<<<(N * DD + 255) / 256, 256>>>(off_ps, off_pacc, out, N);
}

// round 16
// speedup vs baseline: 1.5892x; 1.5892x over previous
#include <cuda_runtime.h>
#include <cstdint>

// ---------------------------------------------------------------------------
// GaussSpatialConv: out[i,:] = softmax_j( -||x_i - y_j||^2 / (2*sigma^2) ) @ fea
// B=1, N=M=12288, D=16, sigma=0.1.
//
// R16: |x|^2 cancels in softmax -> logit l = Yw + x.Y with Y=-2C*y, Yw=C*|y|^2,
// C = -50*log2(e). Two-pass: k_max finds max_j l per query (bitwise-identical
// fma chain), k_acc sums p=exp2(l-lmax) and p*fea. QPT=4 -> grid 576 CTAs =
// exactly one wave at 4 CTAs/SM (launch_bounds(128,4)). y rows stored lane-
// duplicated so the hot loop has zero pack MOVs for y.
// ---------------------------------------------------------------------------

typedef unsigned long long ull;

#define TPB 128
#define QPT 4        // queries per thread (two f32x2 packs)
#define SPL 24       // j-dimension splits (CH = 512 -> 40KB/CTA, L1-resident)
#define DD  16

__device__ __align__(256) float g_scratch[8u << 20];   // 32MB static scratch

// ---- f32x2 helpers ---------------------------------------------------------
__device__ __forceinline__ ull pk2(float lo, float hi) {
    ull r; asm("mov.b64 %0, {%1, %2};" : "=l"(r) : "f"(lo), "f"(hi)); return r;
}
__device__ __forceinline__ void upk2(ull v, float& lo, float& hi) {
    asm("mov.b64 {%0, %1}, %2;" : "=f"(lo), "=f"(hi) : "l"(v));
}
__device__ __forceinline__ ull add2(ull a, ull b) {
    ull r; asm("add.rn.f32x2 %0, %1, %2;" : "=l"(r) : "l"(a), "l"(b)); return r;
}
__device__ __forceinline__ ull fma2(ull a, ull b, ull c) {
    ull r; asm("fma.rn.f32x2 %0, %1, %2, %3;" : "=l"(r) : "l"(a), "l"(b), "l"(c)); return r;
}
__device__ __forceinline__ float ex2(float a) {
    float r; asm("ex2.approx.ftz.f32 %0, %1;" : "=f"(r) : "f"(a)); return r;
}
// logit pair: l = x.Y + Yw for 2 queries packed in lanes.
// r0 = (Y0,Y0 | Y1,Y1), r1 = (Y2,Y2 | Yw,Yw). MUST be the same op sequence in
// k_max and k_acc so that l - lmax <= 0 holds bitwise.
__device__ __forceinline__ ull logit2(ull xx, ull xy, ull xz,
                                      ulonglong2 r0, ulonglong2 r1) {
    ull t = fma2(xz, r1.x, r1.y);
    t = fma2(xy, r0.y, t);
    t = fma2(xx, r0.x, t);
    return t;
}

// ---- k_prep: y8[2j] = (Y0,Y0,Y1,Y1), y8[2j+1] = (Y2,Y2,Yw,Yw) --------------
__global__ void k_prep(const float* __restrict__ y, long long off_y8, int M) {
    float4* y8 = reinterpret_cast<float4*>(g_scratch + off_y8);
    int j = blockIdx.x * blockDim.x + threadIdx.x;
    if (j < M) {
        const float C   = -72.13475204444817f;   // -50 * log2(e)
        const float m2C = 144.26950408889634f;   // -2C
        float a = y[3 * j], b = y[3 * j + 1], c = y[3 * j + 2];
        float Y0 = m2C * a, Y1 = m2C * b, Y2 = m2C * c;
        float Yw = C * (a * a + b * b + c * c);
        y8[2 * j]     = make_float4(Y0, Y0, Y1, Y1);
        y8[2 * j + 1] = make_float4(Y2, Y2, Yw, Yw);
    }
}

// ---- k_max: partial max of logit over this CTA's j-chunk -------------------
__global__ void __launch_bounds__(TPB, 4) k_max(
    const float* __restrict__ x,
    long long off_y8, long long off_pmax,
    int N, int M, int CH)
{
    const ulonglong2* __restrict__ y8 =
        reinterpret_cast<const ulonglong2*>(g_scratch + off_y8);
    float* __restrict__ pmax = g_scratch + off_pmax;

    int s  = blockIdx.x % SPL;
    int qb = blockIdx.x / SPL;
    int i0 = (qb * TPB + threadIdx.x) * QPT;
    int a0 = min(i0,     N - 1), a1 = min(i0 + 1, N - 1);
    int a2 = min(i0 + 2, N - 1), a3 = min(i0 + 3, N - 1);

    ull xxA = pk2(x[3 * a0],     x[3 * a1]);
    ull xyA = pk2(x[3 * a0 + 1], x[3 * a1 + 1]);
    ull xzA = pk2(x[3 * a0 + 2], x[3 * a1 + 2]);
    ull xxB = pk2(x[3 * a2],     x[3 * a3]);
    ull xyB = pk2(x[3 * a2 + 1], x[3 * a3 + 1]);
    ull xzB = pk2(x[3 * a2 + 2], x[3 * a3 + 2]);

    int j0 = s * CH;
    int j1 = min(M, j0 + CH);
    float m0 = -3.4e38f, m1 = -3.4e38f, m2 = -3.4e38f, m3 = -3.4e38f;

    #pragma unroll 2
    for (int j = j0; j < j1; ++j) {
        ulonglong2 r0 = y8[2 * j];
        ulonglong2 r1 = y8[2 * j + 1];
        ull tA = logit2(xxA, xyA, xzA, r0, r1);
        ull tB = logit2(xxB, xyB, xzB, r0, r1);
        float l0, l1, l2, l3;
        upk2(tA, l0, l1);
        upk2(tB, l2, l3);
        m0 = fmaxf(m0, l0); m1 = fmaxf(m1, l1);
        m2 = fmaxf(m2, l2); m3 = fmaxf(m3, l3);
    }
    size_t base = (size_t)s * N;
    if (i0     < N) pmax[base + i0]     = m0;
    if (i0 + 1 < N) pmax[base + i0 + 1] = m1;
    if (i0 + 2 < N) pmax[base + i0 + 2] = m2;
    if (i0 + 3 < N) pmax[base + i0 + 3] = m3;
}

// ---- k_acc: partial softmax numerator/denominator --------------------------
__global__ void __launch_bounds__(TPB, 4) k_acc(
    const float* __restrict__ x,
    const ulonglong2* __restrict__ fea,   // M rows x 4 x ulonglong2 (16 floats)
    long long off_y8, long long off_pmax, long long off_ps, long long off_pacc,
    int N, int M, int CH)
{
    const ulonglong2* __restrict__ y8 =
        reinterpret_cast<const ulonglong2*>(g_scratch + off_y8);
    const float* __restrict__ pmax = g_scratch + off_pmax;
    float* __restrict__ ps   = g_scratch + off_ps;
    float* __restrict__ pacc = g_scratch + off_pacc;

    int s  = blockIdx.x % SPL;
    int qb = blockIdx.x / SPL;
    int i0 = (qb * TPB + threadIdx.x) * QPT;
    int a0 = min(i0,     N - 1), a1 = min(i0 + 1, N - 1);
    int a2 = min(i0 + 2, N - 1), a3 = min(i0 + 3, N - 1);

    ull xxA = pk2(x[3 * a0],     x[3 * a1]);
    ull xyA = pk2(x[3 * a0 + 1], x[3 * a1 + 1]);
    ull xzA = pk2(x[3 * a0 + 2], x[3 * a1 + 2]);
    ull xxB = pk2(x[3 * a2],     x[3 * a3]);
    ull xyB = pk2(x[3 * a2 + 1], x[3 * a3 + 1]);
    ull xzB = pk2(x[3 * a2 + 2], x[3 * a3 + 2]);

    // global max logit per query
    float g0 = -3.4e38f, g1 = -3.4e38f, g2 = -3.4e38f, g3 = -3.4e38f;
    #pragma unroll
    for (int sp = 0; sp < SPL; ++sp) {
        size_t b = (size_t)sp * N;
        g0 = fmaxf(g0, pmax[b + a0]); g1 = fmaxf(g1, pmax[b + a1]);
        g2 = fmaxf(g2, pmax[b + a2]); g3 = fmaxf(g3, pmax[b + a3]);
    }
    ull KA = pk2(-g0, -g1);
    ull KB = pk2(-g2, -g3);

    ull A[4][8];
    #pragma unroll
    for (int q = 0; q < 4; ++q)
        #pragma unroll
        for (int k = 0; k < 8; ++k) A[q][k] = 0ull;
    float s0 = 0.f, s1 = 0.f, s2 = 0.f, s3 = 0.f;

    int j0 = s * CH;
    int j1 = min(M, j0 + CH);

    #pragma unroll 2
    for (int j = j0; j < j1; ++j) {
        ulonglong2 r0 = y8[2 * j];
        ulonglong2 r1 = y8[2 * j + 1];
        // identical op sequence to k_max -> arg <= 0 bitwise-guaranteed
        ull argA = add2(logit2(xxA, xyA, xzA, r0, r1), KA);
        ull argB = add2(logit2(xxB, xyB, xzB, r0, r1), KB);
        float e0, e1, e2, e3;
        upk2(argA, e0, e1);
        upk2(argB, e2, e3);
        float p0 = ex2(e0), p1 = ex2(e1), p2 = ex2(e2), p3 = ex2(e3);
        s0 += p0; s1 += p1; s2 += p2; s3 += p3;
        ull pp[4];
        pp[0] = pk2(p0, p0); pp[1] = pk2(p1, p1);
        pp[2] = pk2(p2, p2); pp[3] = pk2(p3, p3);

        const ulonglong2* fr = fea + (size_t)j * 4;
        {   // dims 0..7
            ulonglong2 fa = fr[0], fb = fr[1];
            #pragma unroll
            for (int q = 0; q < 4; ++q) {
                A[q][0] = fma2(pp[q], fa.x, A[q][0]);
                A[q][1] = fma2(pp[q], fa.y, A[q][1]);
                A[q][2] = fma2(pp[q], fb.x, A[q][2]);
                A[q][3] = fma2(pp[q], fb.y, A[q][3]);
            }
        }
        {   // dims 8..15
            ulonglong2 fa = fr[2], fb = fr[3];
            #pragma unroll
            for (int q = 0; q < 4; ++q) {
                A[q][4] = fma2(pp[q], fa.x, A[q][4]);
                A[q][5] = fma2(pp[q], fa.y, A[q][5]);
                A[q][6] = fma2(pp[q], fb.x, A[q][6]);
                A[q][7] = fma2(pp[q], fb.y, A[q][7]);
            }
        }
    }

    float sv[4] = {s0, s1, s2, s3};
    #pragma unroll
    for (int q = 0; q < 4; ++q) {
        int i = i0 + q;
        if (i < N) {
            ps[(size_t)s * N + i] = sv[q];
            float4* dst = reinterpret_cast<float4*>(
                pacc + ((size_t)s * N + i) * DD);
            #pragma unroll
            for (int k = 0; k < 4; ++k) {
                float lo0, hi0, lo1, hi1;
                upk2(A[q][2 * k],     lo0, hi0);
                upk2(A[q][2 * k + 1], lo1, hi1);
                dst[k] = make_float4(lo0, hi0, lo1, hi1);
            }
        }
    }
}

// ---- k_norm: reduce over splits and normalize (float4 per thread) ----------
__global__ void k_norm(long long off_ps, long long off_pacc,
                       float* __restrict__ out, int N)
{
    const float*  __restrict__ ps   = g_scratch + off_ps;
    const float4* __restrict__ pacc =
        reinterpret_cast<const float4*>(g_scratch + off_pacc);
    int t = blockIdx.x * blockDim.x + threadIdx.x;   // one float4 of output
    if (t >= N * 4) return;
    int i = t >> 2;          // query
    int q = t & 3;           // dim quad
    float st = 0.f;
    float4 at = make_float4(0.f, 0.f, 0.f, 0.f);
    #pragma unroll
    for (int sp = 0; sp < SPL; ++sp) {
        st += ps[(size_t)sp * N + i];
        float4 v = pacc[((size_t)sp * N + i) * 4 + q];
        at.x += v.x; at.y += v.y; at.z += v.z; at.w += v.w;
    }
    float inv = 1.0f / st;
    reinterpret_cast<float4*>(out)[t] =
        make_float4(at.x * inv, at.y * inv, at.z * inv, at.w * inv);
}

// ---------------------------------------------------------------------------
extern "C" void kernel_launch(void* const* d_in, const int* in_sizes, int n_in,
                              void* d_out, int out_size) {
    const float* x   = (const float*)d_in[0];   // [N,3]
    const float* y   = (const float*)d_in[1];   // [M,3]
    const float* fea = (const float*)d_in[2];   // [M,16]
    float* out = (float*)d_out;                 // [N,16]

    int N = in_sizes[0] / 3;
    int M = in_sizes[1] / 3;

    auto r4 = [](long long v) { return (v + 3) & ~3LL; };
    long long off_y8   = 0;                                  // 8*M floats
    long long off_pmax = r4(off_y8 + 8LL * M);               // SPL*N
    long long off_ps   = r4(off_pmax + (long long)SPL * N);  // SPL*N
    long long off_pacc = r4(off_ps + (long long)SPL * N);    // SPL*N*16
    // total ~= 8M + 2*SPL*N + 16*SPL*N ~= 5.5M floats < 8M capacity

    int CH = (M + SPL - 1) / SPL;                  // 512
    int QB = (N + TPB * QPT - 1) / (TPB * QPT);    // 24
    // grid = QB*SPL = 576 CTAs -> exactly 1 wave at 4 CTAs/SM on 148 SMs

    k_prep<<<(M + 255) / 256, 256>>>(y, off_y8, M);
    k_max<<<QB * SPL, TPB>>>(x, off_y8, off_pmax, N, M, CH);
    k_acc<<<QB * SPL, TPB>>>(x, (const ulonglong2*)fea,
                             off_y8, off_pmax, off_ps, off_pacc, N, M, CH);
    k_norm<<<(N * 4 + 255) / 256, 256>>>(off_ps, off_pacc, out, N);
}

// round 17
// speedup vs baseline: 1.6000x; 1.0068x over previous
#include <cuda_runtime.h>
#include <cstdint>

// ---------------------------------------------------------------------------
// GaussSpatialConv: out[i,:] = softmax_j( -||x_i - y_j||^2 / (2*sigma^2) ) @ fea
// B=1, N=M=12288, D=16, sigma=0.1.
//
// R16: |x|^2 cancels in softmax -> logit l = Yw + x.Y with Y=-2C*y, Yw=C*|y|^2,
// C = -50*log2(e). Two-pass: k_max finds max_j l per query (bitwise-identical
// fma chain), k_acc sums p=exp2(l-lmax) and p*fea. QPT=4 -> grid 576 CTAs =
// exactly one wave at 4 CTAs/SM (launch_bounds(128,4)). y rows stored lane-
// duplicated so the hot loop has zero pack MOVs for y.
// ---------------------------------------------------------------------------

typedef unsigned long long ull;

#define TPB 128
#define QPT 4        // queries per thread (two f32x2 packs)
#define SPL 24       // j-dimension splits (CH = 512 -> 40KB/CTA, L1-resident)
#define DD  16

__device__ __align__(256) float g_scratch[8u << 20];   // 32MB static scratch

// ---- f32x2 helpers ---------------------------------------------------------
__device__ __forceinline__ ull pk2(float lo, float hi) {
    ull r; asm("mov.b64 %0, {%1, %2};" : "=l"(r) : "f"(lo), "f"(hi)); return r;
}
__device__ __forceinline__ void upk2(ull v, float& lo, float& hi) {
    asm("mov.b64 {%0, %1}, %2;" : "=f"(lo), "=f"(hi) : "l"(v));
}
__device__ __forceinline__ ull add2(ull a, ull b) {
    ull r; asm("add.rn.f32x2 %0, %1, %2;" : "=l"(r) : "l"(a), "l"(b)); return r;
}
__device__ __forceinline__ ull fma2(ull a, ull b, ull c) {
    ull r; asm("fma.rn.f32x2 %0, %1, %2, %3;" : "=l"(r) : "l"(a), "l"(b), "l"(c)); return r;
}
__device__ __forceinline__ float ex2(float a) {
    float r; asm("ex2.approx.ftz.f32 %0, %1;" : "=f"(r) : "f"(a)); return r;
}
// logit pair: l = x.Y + Yw for 2 queries packed in lanes.
// r0 = (Y0,Y0 | Y1,Y1), r1 = (Y2,Y2 | Yw,Yw). MUST be the same op sequence in
// k_max and k_acc so that l - lmax <= 0 holds bitwise.
__device__ __forceinline__ ull logit2(ull xx, ull xy, ull xz,
                                      ulonglong2 r0, ulonglong2 r1) {
    ull t = fma2(xz, r1.x, r1.y);
    t = fma2(xy, r0.y, t);
    t = fma2(xx, r0.x, t);
    return t;
}

// ---- k_prep: y8[2j] = (Y0,Y0,Y1,Y1), y8[2j+1] = (Y2,Y2,Yw,Yw) --------------
__global__ void k_prep(const float* __restrict__ y, long long off_y8, int M) {
    float4* y8 = reinterpret_cast<float4*>(g_scratch + off_y8);
    int j = blockIdx.x * blockDim.x + threadIdx.x;
    if (j < M) {
        const float C   = -72.13475204444817f;   // -50 * log2(e)
        const float m2C = 144.26950408889634f;   // -2C
        float a = y[3 * j], b = y[3 * j + 1], c = y[3 * j + 2];
        float Y0 = m2C * a, Y1 = m2C * b, Y2 = m2C * c;
        float Yw = C * (a * a + b * b + c * c);
        y8[2 * j]     = make_float4(Y0, Y0, Y1, Y1);
        y8[2 * j + 1] = make_float4(Y2, Y2, Yw, Yw);
    }
}

// ---- k_max: partial max of logit over this CTA's j-chunk -------------------
__global__ void __launch_bounds__(TPB, 4) k_max(
    const float* __restrict__ x,
    long long off_y8, long long off_pmax,
    int N, int M, int CH)
{
    const ulonglong2* __restrict__ y8 =
        reinterpret_cast<const ulonglong2*>(g_scratch + off_y8);
    float* __restrict__ pmax = g_scratch + off_pmax;

    int s  = blockIdx.x % SPL;
    int qb = blockIdx.x / SPL;
    int i0 = (qb * TPB + threadIdx.x) * QPT;
    int a0 = min(i0,     N - 1), a1 = min(i0 + 1, N - 1);
    int a2 = min(i0 + 2, N - 1), a3 = min(i0 + 3, N - 1);

    ull xxA = pk2(x[3 * a0],     x[3 * a1]);
    ull xyA = pk2(x[3 * a0 + 1], x[3 * a1 + 1]);
    ull xzA = pk2(x[3 * a0 + 2], x[3 * a1 + 2]);
    ull xxB = pk2(x[3 * a2],     x[3 * a3]);
    ull xyB = pk2(x[3 * a2 + 1], x[3 * a3 + 1]);
    ull xzB = pk2(x[3 * a2 + 2], x[3 * a3 + 2]);

    int j0 = s * CH;
    int j1 = min(M, j0 + CH);
    float m0 = -3.4e38f, m1 = -3.4e38f, m2 = -3.4e38f, m3 = -3.4e38f;

    #pragma unroll 2
    for (int j = j0; j < j1; ++j) {
        ulonglong2 r0 = y8[2 * j];
        ulonglong2 r1 = y8[2 * j + 1];
        ull tA = logit2(xxA, xyA, xzA, r0, r1);
        ull tB = logit2(xxB, xyB, xzB, r0, r1);
        float l0, l1, l2, l3;
        upk2(tA, l0, l1);
        upk2(tB, l2, l3);
        m0 = fmaxf(m0, l0); m1 = fmaxf(m1, l1);
        m2 = fmaxf(m2, l2); m3 = fmaxf(m3, l3);
    }
    size_t base = (size_t)s * N;
    if (i0     < N) pmax[base + i0]     = m0;
    if (i0 + 1 < N) pmax[base + i0 + 1] = m1;
    if (i0 + 2 < N) pmax[base + i0 + 2] = m2;
    if (i0 + 3 < N) pmax[base + i0 + 3] = m3;
}

// ---- k_acc: partial softmax numerator/denominator --------------------------
__global__ void __launch_bounds__(TPB, 4) k_acc(
    const float* __restrict__ x,
    const ulonglong2* __restrict__ fea,   // M rows x 4 x ulonglong2 (16 floats)
    long long off_y8, long long off_pmax, long long off_ps, long long off_pacc,
    int N, int M, int CH)
{
    const ulonglong2* __restrict__ y8 =
        reinterpret_cast<const ulonglong2*>(g_scratch + off_y8);
    const float* __restrict__ pmax = g_scratch + off_pmax;
    float* __restrict__ ps   = g_scratch + off_ps;
    float* __restrict__ pacc = g_scratch + off_pacc;

    int s  = blockIdx.x % SPL;
    int qb = blockIdx.x / SPL;
    int i0 = (qb * TPB + threadIdx.x) * QPT;
    int a0 = min(i0,     N - 1), a1 = min(i0 + 1, N - 1);
    int a2 = min(i0 + 2, N - 1), a3 = min(i0 + 3, N - 1);

    ull xxA = pk2(x[3 * a0],     x[3 * a1]);
    ull xyA = pk2(x[3 * a0 + 1], x[3 * a1 + 1]);
    ull xzA = pk2(x[3 * a0 + 2], x[3 * a1 + 2]);
    ull xxB = pk2(x[3 * a2],     x[3 * a3]);
    ull xyB = pk2(x[3 * a2 + 1], x[3 * a3 + 1]);
    ull xzB = pk2(x[3 * a2 + 2], x[3 * a3 + 2]);

    // global max logit per query
    float g0 = -3.4e38f, g1 = -3.4e38f, g2 = -3.4e38f, g3 = -3.4e38f;
    #pragma unroll
    for (int sp = 0; sp < SPL; ++sp) {
        size_t b = (size_t)sp * N;
        g0 = fmaxf(g0, pmax[b + a0]); g1 = fmaxf(g1, pmax[b + a1]);
        g2 = fmaxf(g2, pmax[b + a2]); g3 = fmaxf(g3, pmax[b + a3]);
    }
    ull KA = pk2(-g0, -g1);
    ull KB = pk2(-g2, -g3);

    ull A[4][8];
    #pragma unroll
    for (int q = 0; q < 4; ++q)
        #pragma unroll
        for (int k = 0; k < 8; ++k) A[q][k] = 0ull;
    float s0 = 0.f, s1 = 0.f, s2 = 0.f, s3 = 0.f;

    int j0 = s * CH;
    int j1 = min(M, j0 + CH);

    #pragma unroll 2
    for (int j = j0; j < j1; ++j) {
        ulonglong2 r0 = y8[2 * j];
        ulonglong2 r1 = y8[2 * j + 1];
        // identical op sequence to k_max -> arg <= 0 bitwise-guaranteed
        ull argA = add2(logit2(xxA, xyA, xzA, r0, r1), KA);
        ull argB = add2(logit2(xxB, xyB, xzB, r0, r1), KB);
        float e0, e1, e2, e3;
        upk2(argA, e0, e1);
        upk2(argB, e2, e3);
        float p0 = ex2(e0), p1 = ex2(e1), p2 = ex2(e2), p3 = ex2(e3);
        s0 += p0; s1 += p1; s2 += p2; s3 += p3;
        ull pp[4];
        pp[0] = pk2(p0, p0); pp[1] = pk2(p1, p1);
        pp[2] = pk2(p2, p2); pp[3] = pk2(p3, p3);

        const ulonglong2* fr = fea + (size_t)j * 4;
        {   // dims 0..7
            ulonglong2 fa = fr[0], fb = fr[1];
            #pragma unroll
            for (int q = 0; q < 4; ++q) {
                A[q][0] = fma2(pp[q], fa.x, A[q][0]);
                A[q][1] = fma2(pp[q], fa.y, A[q][1]);
                A[q][2] = fma2(pp[q], fb.x, A[q][2]);
                A[q][3] = fma2(pp[q], fb.y, A[q][3]);
            }
        }
        {   // dims 8..15
            ulonglong2 fa = fr[2], fb = fr[3];
            #pragma unroll
            for (int q = 0; q < 4; ++q) {
                A[q][4] = fma2(pp[q], fa.x, A[q][4]);
                A[q][5] = fma2(pp[q], fa.y, A[q][5]);
                A[q][6] = fma2(pp[q], fb.x, A[q][6]);
                A[q][7] = fma2(pp[q], fb.y, A[q][7]);
            }
        }
    }

    float sv[4] = {s0, s1, s2, s3};
    #pragma unroll
    for (int q = 0; q < 4; ++q) {
        int i = i0 + q;
        if (i < N) {
            ps[(size_t)s * N + i] = sv[q];
            float4* dst = reinterpret_cast<float4*>(
                pacc + ((size_t)s * N + i) * DD);
            #pragma unroll
            for (int k = 0; k < 4; ++k) {
                float lo0, hi0, lo1, hi1;
                upk2(A[q][2 * k],     lo0, hi0);
                upk2(A[q][2 * k + 1], lo1, hi1);
                dst[k] = make_float4(lo0, hi0, lo1, hi1);
            }
        }
    }
}

// ---- k_norm: reduce over splits and normalize (float4 per thread) ----------
__global__ void k_norm(long long off_ps, long long off_pacc,
                       float* __restrict__ out, int N)
{
    const float*  __restrict__ ps   = g_scratch + off_ps;
    const float4* __restrict__ pacc =
        reinterpret_cast<const float4*>(g_scratch + off_pacc);
    int t = blockIdx.x * blockDim.x + threadIdx.x;   // one float4 of output
    if (t >= N * 4) return;
    int i = t >> 2;          // query
    int q = t & 3;           // dim quad
    float st = 0.f;
    float4 at = make_float4(0.f, 0.f, 0.f, 0.f);
    #pragma unroll
    for (int sp = 0; sp < SPL; ++sp) {
        st += ps[(size_t)sp * N + i];
        float4 v = pacc[((size_t)sp * N + i) * 4 + q];
        at.x += v.x; at.y += v.y; at.z += v.z; at.w += v.w;
    }
    float inv = 1.0f / st;
    reinterpret_cast<float4*>(out)[t] =
        make_float4(at.x * inv, at.y * inv, at.z * inv, at.w * inv);
}

// ---------------------------------------------------------------------------
extern "C" void kernel_launch(void* const* d_in, const int* in_sizes, int n_in,
                              void* d_out, int out_size) {
    const float* x   = (const float*)d_in[0];   // [N,3]
    const float* y   = (const float*)d_in[1];   // [M,3]
    const float* fea = (const float*)d_in[2];   // [M,16]
    float* out = (float*)d_out;                 // [N,16]

    int N = in_sizes[0] / 3;
    int M = in_sizes[1] / 3;

    auto r4 = [](long long v) { return (v + 3) & ~3LL; };
    long long off_y8   = 0;                                  // 8*M floats
    long long off_pmax = r4(off_y8 + 8LL * M);               // SPL*N
    long long off_ps   = r4(off_pmax + (long long)SPL * N);  // SPL*N
    long long off_pacc = r4(off_ps + (long long)SPL * N);    // SPL*N*16
    // total ~= 8M + 2*SPL*N + 16*SPL*N ~= 5.5M floats < 8M capacity

    int CH = (M + SPL - 1) / SPL;                  // 512
    int QB = (N + TPB * QPT - 1) / (TPB * QPT);    // 24
    // grid = QB*SPL = 576 CTAs -> exactly 1 wave at 4 CTAs/SM on 148 SMs

    k_prep<<<(M + 255) / 256, 256>>>(y, off_y8, M);
    k_max<<<QB * SPL, TPB>>>(x, off_y8, off_pmax, N, M, CH);
    k_acc<<<QB * SPL, TPB>>>(x, (const ulonglong2*)fea,
                             off_y8, off_pmax, off_ps, off_pacc, N, M, CH);
    k_norm<<<(N * 4 + 255) / 256, 256>>>(off_ps, off_pacc, out, N);
}